// round 17
// baseline (speedup 1.0000x reference)
#include <cuda_runtime.h>
#include <cuda_fp16.h>
#include <cstdint>

#define N_SEL   192
#define N_PTS   2048
#define C_IN    256
#define C_OUT   256
#define N_TILES 8

#define BM 64
#define BN 256
#define BK 32
#define NSLABS (C_IN / BK)   // 8
#define THREADS 256

#define ROWA   80            // A tile row: 32 fp16 (64B) + 16 pad
#define ROWBK  528           // B tile row ([K][N]): 256 fp16 (512B) + 16 pad; 33x16B, %8=1

// dynamic smem layout
#define SM_BIAS  0                         // 256 f32 = 1024 B
#define SM_AH    1024                      // 2 stages x 64 rows x 80 B
#define A_STG    (BM * ROWA)               // 5120
#define SM_B     (SM_AH + 2 * A_STG)       // 11264; 4 stages x 32 k-rows x 528 B
#define B_STG    (BK * ROWBK)              // 16896
#define SM_TOTAL (SM_B + 4 * B_STG)        // 78848

// gathered fp16 weights, ORIGINAL [K][N] order: [n_sel][K=C_IN][N=C_OUT]
__device__ __half g_wt[(size_t)N_SEL * C_IN * C_OUT];

__device__ __forceinline__ uint32_t smem_u32(const void* p) {
    uint32_t a;
    asm("{ .reg .u64 t; cvta.to.shared.u64 t, %1; cvt.u32.u64 %0, t; }" : "=r"(a) : "l"(p));
    return a;
}
__device__ __forceinline__ void cp16(uint32_t dst, const void* src) {
    asm volatile("cp.async.cg.shared.global [%0], [%1], 16;" :: "r"(dst), "l"(src));
}
__device__ __forceinline__ uint32_t pack_h2(float a, float b) {
    uint32_t r;
    asm("cvt.rn.f16x2.f32 %0, %2, %1;" : "=r"(r) : "f"(a), "f"(b));
    return r;
}
__device__ __forceinline__ void ldmx4(uint32_t addr, uint32_t& r0, uint32_t& r1,
                                      uint32_t& r2, uint32_t& r3) {
    asm volatile("ldmatrix.sync.aligned.m8n8.x4.shared.b16 {%0,%1,%2,%3}, [%4];"
                 : "=r"(r0), "=r"(r1), "=r"(r2), "=r"(r3) : "r"(addr));
}
__device__ __forceinline__ void ldmx4t(uint32_t addr, uint32_t& r0, uint32_t& r1,
                                       uint32_t& r2, uint32_t& r3) {
    asm volatile("ldmatrix.sync.aligned.m8n8.x4.trans.shared.b16 {%0,%1,%2,%3}, [%4];"
                 : "=r"(r0), "=r"(r1), "=r"(r2), "=r"(r3) : "r"(addr));
}
__device__ __forceinline__ void mma_f16(float* c, const uint32_t* a, const uint32_t* b) {
    asm volatile("mma.sync.aligned.m16n8k16.row.col.f32.f16.f16.f32 "
                 "{%0,%1,%2,%3}, {%4,%5,%6,%7}, {%8,%9}, {%0,%1,%2,%3};"
                 : "+f"(c[0]), "+f"(c[1]), "+f"(c[2]), "+f"(c[3])
                 : "r"(a[0]), "r"(a[1]), "r"(a[2]), "r"(a[3]), "r"(b[0]), "r"(b[1]));
}

// ---------------- kernel 1: gather + fp16 convert of W (no transpose) ----------------
__global__ void wt_prep_kernel(const float* __restrict__ weight,
                               const int* __restrict__ indices,
                               const int* __restrict__ t_ptr) {
    const int n = blockIdx.y;
    const int t = (t_ptr != nullptr) ? *t_ptr : 3;
    const int idx = indices[n];
    const float* W = weight + (((size_t)idx * N_TILES + t) * C_IN) * C_OUT;
    __half* o = g_wt + (size_t)n * C_IN * C_OUT;

    const int base4 = blockIdx.x * 2048;     // float4 units
    #pragma unroll
    for (int j = 0; j < 8; j++) {
        const int g = base4 + threadIdx.x + j * 256;
        const float4 f = reinterpret_cast<const float4*>(W)[g];
        uint2 v;
        v.x = pack_h2(f.x, f.y);
        v.y = pack_h2(f.z, f.w);
        reinterpret_cast<uint2*>(o)[g] = v;
    }
}

// ---------------- kernel 2: fp16 mma.sync GEMM, 4-deep B ring, batched fragments ----------------
__global__ __launch_bounds__(THREADS, 2)
void gemm_f16_kernel(const float* __restrict__ x,
                     const float* __restrict__ bias,
                     const int* __restrict__ indices,
                     const int* __restrict__ t_ptr,
                     float* __restrict__ out) {
    extern __shared__ __align__(16) unsigned char smem[];
    const uint32_t sa = smem_u32(smem);

    const int tid  = threadIdx.x;
    const int lane = tid & 31;
    const int wid  = tid >> 5;          // 0..7

    const int n_sel = blockIdx.y;
    const int m0    = blockIdx.x * BM;
    const int t   = (t_ptr != nullptr) ? *t_ptr : 3;
    const int idx = indices[n_sel];

    const float* A = x + (size_t)n_sel * N_PTS * C_IN + (size_t)m0 * C_IN;
    const __half* Wn = g_wt + (size_t)n_sel * C_IN * C_OUT;   // [K][N]

    // B cp.async: slab = 32 k-rows x 512B = 1024 x 16B chunks, 4/thread
    auto issue_B = [&](int s) {
        const uint32_t base = sa + SM_B + (uint32_t)(s & 3) * B_STG;
        const int k0 = s * BK;
        #pragma unroll
        for (int i = 0; i < 4; i++) {
            const int c = tid + i * THREADS;
            const int r = c >> 5, seg = c & 31;
            cp16(base + (uint32_t)(r * ROWBK + seg * 16),
                 Wn + (size_t)(k0 + r) * C_OUT + seg * 8);
        }
        asm volatile("cp.async.commit_group;" ::: "memory");
    };

    issue_B(0);
    issue_B(1);
    issue_B(2);

    // bias -> smem (THREADS == C_OUT)
    float* bs = (float*)(smem + SM_BIAS);
    bs[tid] = bias[((size_t)idx * N_TILES + t) * C_OUT + tid];

    // warp tiling: 2 m-warps x 4 n-warps; warp tile 32x64
    const int m_off = (wid >> 2) * 32;
    const int n_off = (wid & 3) * 64;

    float acc[2][8][4];
    #pragma unroll
    for (int i = 0; i < 2; i++)
        #pragma unroll
        for (int j = 0; j < 8; j++)
            #pragma unroll
            for (int q = 0; q < 4; q++)
                acc[i][j][q] = 0.0f;

    // per-thread A load mapping
    const int ar  = tid >> 2;            // row 0..63
    const int as8 = (tid & 3) * 8;       // col start (floats)

    float4 a0, a1;
    {
        const float* src = A + (size_t)ar * C_IN + as8;
        a0 = *reinterpret_cast<const float4*>(src);
        a1 = *reinterpret_cast<const float4*>(src + 4);
    }

    // trans-B lane geometry
    const int bq      = lane >> 3;
    const int bk_lane = (bq & 1) * 8 + (lane & 7);
    const int bn_oct  = ((bq >> 1) & 1) * 8;
    // A lane geometry
    const int arowL = lane & 15;
    const int acolL = ((lane >> 4) & 1) * 8;

    for (int s = 0; s < NSLABS; s++) {
        const int stgA = s & 1;

        // convert A regs (slab s) -> fp16 smem stage stgA
        {
            const uint32_t off = (uint32_t)(SM_AH + stgA * A_STG + ar * ROWA + (as8 >> 3) * 16);
            uint4 v;
            v.x = pack_h2(a0.x, a0.y);
            v.y = pack_h2(a0.z, a0.w);
            v.z = pack_h2(a1.x, a1.y);
            v.w = pack_h2(a1.z, a1.w);
            *reinterpret_cast<uint4*>(smem + off) = v;
        }

        if (s + 1 < NSLABS) {
            const float* src = A + (size_t)ar * C_IN + (s + 1) * BK + as8;
            a0 = *reinterpret_cast<const float4*>(src);
            a1 = *reinterpret_cast<const float4*>(src + 4);
        }

        const int rem = NSLABS - 1 - s;
        if (rem >= 2)      asm volatile("cp.async.wait_group 2;" ::: "memory");
        else if (rem == 1) asm volatile("cp.async.wait_group 1;" ::: "memory");
        else               asm volatile("cp.async.wait_group 0;" ::: "memory");
        __syncthreads();

        if (s + 3 < NSLABS) issue_B(s + 3);

        const uint32_t aB = sa + SM_AH + (uint32_t)(stgA * A_STG);
        const uint32_t bB = sa + SM_B  + (uint32_t)((s & 3) * B_STG);

        // ---- batch-load ALL B fragments for the slab (2 k-steps x 4 n16-tiles) ----
        uint32_t bf[2][8][2];
        #pragma unroll
        for (int ks2 = 0; ks2 < 2; ks2++) {
            #pragma unroll
            for (int p = 0; p < 4; p++) {
                const int krow = ks2 * 16 + bk_lane;
                const int ncol = n_off + p * 16 + bn_oct;
                ldmx4t(bB + (uint32_t)(krow * ROWBK + ncol * 2),
                       bf[ks2][2 * p][0], bf[ks2][2 * p][1],
                       bf[ks2][2 * p + 1][0], bf[ks2][2 * p + 1][1]);
            }
        }

        // ---- per m-fragment: 2 A loads, then 16 back-to-back MMAs ----
        #pragma unroll
        for (int mf = 0; mf < 2; mf++) {
            const int rowA = m_off + mf * 16 + arowL;
            uint32_t af[2][4];
            ldmx4(aB + (uint32_t)(rowA * ROWA + acolL * 2),
                  af[0][0], af[0][1], af[0][2], af[0][3]);
            ldmx4(aB + (uint32_t)(rowA * ROWA + (16 + acolL) * 2),
                  af[1][0], af[1][1], af[1][2], af[1][3]);
            #pragma unroll
            for (int ks2 = 0; ks2 < 2; ks2++)
                #pragma unroll
                for (int nf = 0; nf < 8; nf++)
                    mma_f16(acc[mf][nf], af[ks2], bf[ks2][nf]);
        }
    }

    // ---- epilogue: + bias, float2 stores ----
    float* Out = out + (size_t)n_sel * N_PTS * C_OUT + (size_t)m0 * C_OUT;
    const int r4 = lane >> 2;
    const int c2 = (lane & 3) * 2;
    #pragma unroll
    for (int mf = 0; mf < 2; mf++) {
        #pragma unroll
        for (int nf = 0; nf < 8; nf++) {
            const int col = n_off + nf * 8 + c2;
            const float bx = bs[col], by = bs[col + 1];
            const int row0 = m_off + mf * 16 + r4;
            float2 o0, o1;
            o0.x = acc[mf][nf][0] + bx; o0.y = acc[mf][nf][1] + by;
            o1.x = acc[mf][nf][2] + bx; o1.y = acc[mf][nf][3] + by;
            *reinterpret_cast<float2*>(Out + (size_t)row0 * C_OUT + col) = o0;
            *reinterpret_cast<float2*>(Out + (size_t)(row0 + 8) * C_OUT + col) = o1;
        }
    }
}

extern "C" void kernel_launch(void* const* d_in, const int* in_sizes, int n_in,
                              void* d_out, int out_size) {
    const float* x       = (const float*)d_in[0];
    const float* weight  = (const float*)d_in[1];
    const float* bias    = (const float*)d_in[2];
    const int*   indices = (const int*)d_in[3];
    const int*   t_ptr   = (n_in > 4) ? (const int*)d_in[4] : nullptr;
    float*       out     = (float*)d_out;

    {
        dim3 grid(8, N_SEL);
        dim3 block(THREADS);
        wt_prep_kernel<<<grid, block>>>(weight, indices, t_ptr);
    }
    {
        cudaFuncSetAttribute(gemm_f16_kernel,
                             cudaFuncAttributeMaxDynamicSharedMemorySize, SM_TOTAL);
        dim3 grid(N_PTS / BM, N_SEL);
        dim3 block(THREADS);
        gemm_f16_kernel<<<grid, block, SM_TOTAL>>>(x, bias, indices, t_ptr, out);
    }
}